// round 3
// baseline (speedup 1.0000x reference)
#include <cuda_runtime.h>
#include <math.h>

// ---------------- static device scratch (allocation-free rule) ----------------
__device__ float g_w1q[320*192*25];
__device__ float g_w2q[192*192*25];
__device__ float g_w3q[192*192*25];
__device__ float g_w4q[192*3*25];
__device__ float g_b1q[192];
__device__ float g_b2q[192];
__device__ float g_b3q[192];
__device__ float g_b4q[3];
__device__ float g_a0[192*96*96];
__device__ float g_a1[192*192*192];
__device__ float g_a2[192*384*384];
__device__ float g_params[24];

typedef unsigned long long ull;

#define FMA_F32X2(d, a, b) \
    asm("fma.rn.f32x2 %0, %1, %2, %0;" : "+l"(d) : "l"(a), "l"(b))
#define PACK_F32X2(d, lo, hi) \
    asm("mov.b64 %0, {%1, %2};" : "=l"(d) : "f"(lo), "f"(hi))
#define UNPACK_F32X2(lo, hi, v) \
    asm("mov.b64 {%0, %1}, %2;" : "=f"(lo), "=f"(hi) : "l"(v))

// ---------------- weight/bias quantization: round-half-even ----------------
__global__ void quant_kernel(const float* __restrict__ src, float* __restrict__ dst, int n) {
    int i = blockIdx.x * blockDim.x + threadIdx.x;
    if (i < n) dst[i] = rintf(src[i]);
}

// ---------------- per-stage fixed-point parameters ----------------
__global__ void prep_kernel(const float* __restrict__ relus,
                            const int* __restrict__ dvds,
                            const int* __restrict__ bitsp) {
    if (threadIdx.x == 0 && blockIdx.x == 0) {
        float B = bitsp ? (float)(*bitsp) : 8.0f;
        float maxv = exp2f(B) - 1.0f;                  // 255
        const int sks[3] = {3, 4, 3};
        for (int i = 0; i < 3; i++) {
            float dv = (float)dvds[i];
            g_params[i*6+0] = exp2f(dv - 10.0f);               // addA = 2^(dv-1-9)
            g_params[i*6+1] = exp2f(9.0f - dv);                // invA = 2^-(dv-9)
            g_params[i*6+2] = rintf((maxv / relus[i]) * 33554432.0f); // clp
            float sk = (float)sks[i];
            g_params[i*6+3] = floorf((relus[i] + exp2f(sk - 1.0f)) * exp2f(-sk)); // scl
            g_params[i*6+4] = exp2f(24.0f - sk);               // addB = 2^(15+9-sk)
            g_params[i*6+5] = exp2f(sk - 25.0f);               // invB = 2^-(16+9-sk)
        }
        float dv3 = (float)dvds[3];
        g_params[18] = exp2f(dv3 - 9.0f);                      // stage3 addA
        g_params[19] = exp2f(8.0f - dv3);                      // stage3 invA
    }
}

// ---------------- universal transposed-conv (k=5,s=2,p=2,op=1) + quant epilogue ----
// Gather form: out(2y+py, 2x+px) = sum_ci sum_{dy,dx} in(y+dy, x+dx) * W[ci][co][...]
// FFMA2 version: output rows are processed in pairs (r, r+PH) packed into f32x2.
// Input tile staged in pair-slot layout: slots (2b, 2b+1) hold rows (b, b+PH)
// so each activation pair is one aligned LDS.64.
template<int COPB, int NYSUB>
__global__ void __launch_bounds__(256, 2) deconv_kernel(
    const float* __restrict__ in, float* __restrict__ out,
    const float* __restrict__ wq, const float* __restrict__ bq,
    const float* __restrict__ mul,
    int CIN, int COUT, int H, int W, int stage)
{
    constexpr int YPW   = 8 / NYSUB;       // input rows per warp
    constexpr int PH    = YPW / 2;         // pair offset
    constexpr int NSLOT = 2 * (10 - PH);   // pair slots per column
    constexpr int CST   = NSLOT + 2;       // padded column stride (even, conflict-free)

    __shared__ __align__(16) float sIn[8 * 34 * CST];
    __shared__ __align__(16) float sW[8][COPB][28];

    const int tid  = threadIdx.x;
    const int lane = tid & 31;
    const int wid  = tid >> 5;
    const int co_local = wid % COPB;
    const int ysub     = wid / COPB;
    const int x0   = blockIdx.x * 32;
    const int y0   = blockIdx.y * 8;
    const int co   = blockIdx.z * COPB + co_local;
    const int HW   = H * W;
    const int base = ysub * YPW;           // local base row for this warp

    ull acc2[PH][4];
    #pragma unroll
    for (int i = 0; i < PH; i++)
        #pragma unroll
        for (int j = 0; j < 4; j++) acc2[i][j] = 0ull;

    for (int cib = 0; cib < CIN; cib += 8) {
        __syncthreads();
        // stage input tile into pair-slot layout; rows y0-1..y0+8, OOB -> 0
        for (int idx = tid; idx < 8 * NSLOT * 34; idx += 256) {
            int c  = idx % 34;
            int t  = idx / 34;
            int s  = t % NSLOT;
            int ci = t / NSLOT;
            int row = (s & 1) ? (s >> 1) + PH : (s >> 1);
            int gy  = y0 - 1 + row;
            int gx  = x0 - 1 + c;
            float v = 0.f;
            if ((unsigned)gy < (unsigned)H && (unsigned)gx < (unsigned)W)
                v = in[(size_t)(cib + ci) * HW + (size_t)gy * W + gx];
            sIn[(ci * 34 + c) * CST + s] = v;
        }
        // stage weights [ci][co_local][25]
        for (int idx = tid; idx < 8 * COPB * 25; idx += 256) {
            int ci  = idx / (COPB * 25);
            int rem = idx - ci * (COPB * 25);
            int c8  = rem / 25;
            int t   = rem - c8 * 25;
            int gco = blockIdx.z * COPB + c8;
            sW[ci][c8][t] = (gco < COUT)
                ? wq[((size_t)(cib + ci) * COUT + gco) * 25 + t] : 0.f;
        }
        __syncthreads();

        if (co < COUT) {
            for (int ci = 0; ci < 8; ci++) {
                // duplicate 25 weights into f32x2 pairs
                const float4* wv = reinterpret_cast<const float4*>(&sW[ci][co_local][0]);
                float4 q0 = wv[0], q1 = wv[1], q2 = wv[2], q3 = wv[3], q4 = wv[4], q5 = wv[5];
                float wlast = sW[ci][co_local][24];
                ull wd[25];
                {
                    float wr[25] = {q0.x,q0.y,q0.z,q0.w, q1.x,q1.y,q1.z,q1.w,
                                    q2.x,q2.y,q2.z,q2.w, q3.x,q3.y,q3.z,q3.w,
                                    q4.x,q4.y,q4.z,q4.w, q5.x,q5.y,q5.z,q5.w, wlast};
                    #pragma unroll
                    for (int t = 0; t < 25; t++) PACK_F32X2(wd[t], wr[t], wr[t]);
                }

                const float* sInc = &sIn[ci * 34 * CST];
                // pair load: rows (base+b, base+b+PH) at col lane+dc
                #define PAIR_AT(b, dc) \
                    (*reinterpret_cast<const ull*>(&sInc[(lane + (dc)) * CST + 2 * (base + (b))]))

                ull P00 = PAIR_AT(0,0), P01 = PAIR_AT(0,1), P02 = PAIR_AT(0,2);
                ull P10 = PAIR_AT(1,0), P11 = PAIR_AT(1,1), P12 = PAIR_AT(1,2);
                ull P20 = PAIR_AT(2,0), P21 = PAIR_AT(2,1), P22 = PAIR_AT(2,2);

                #pragma unroll
                for (int p = 0; p < PH; p++) {
                    if (p) {
                        P00 = P10; P01 = P11; P02 = P12;
                        P10 = P20; P11 = P21; P12 = P22;
                        P20 = PAIR_AT(p+2, 0);
                        P21 = PAIR_AT(p+2, 1);
                        P22 = PAIR_AT(p+2, 2);
                    }
                    // (py=0,px=0): 9 taps
                    FMA_F32X2(acc2[p][0], P00, wd[24]);
                    FMA_F32X2(acc2[p][0], P01, wd[22]);
                    FMA_F32X2(acc2[p][0], P02, wd[20]);
                    FMA_F32X2(acc2[p][0], P10, wd[14]);
                    FMA_F32X2(acc2[p][0], P11, wd[12]);
                    FMA_F32X2(acc2[p][0], P12, wd[10]);
                    FMA_F32X2(acc2[p][0], P20, wd[4]);
                    FMA_F32X2(acc2[p][0], P21, wd[2]);
                    FMA_F32X2(acc2[p][0], P22, wd[0]);
                    // (py=0,px=1): 6 taps
                    FMA_F32X2(acc2[p][1], P01, wd[23]);
                    FMA_F32X2(acc2[p][1], P02, wd[21]);
                    FMA_F32X2(acc2[p][1], P11, wd[13]);
                    FMA_F32X2(acc2[p][1], P12, wd[11]);
                    FMA_F32X2(acc2[p][1], P21, wd[3]);
                    FMA_F32X2(acc2[p][1], P22, wd[1]);
                    // (py=1,px=0): 6 taps
                    FMA_F32X2(acc2[p][2], P10, wd[19]);
                    FMA_F32X2(acc2[p][2], P11, wd[17]);
                    FMA_F32X2(acc2[p][2], P12, wd[15]);
                    FMA_F32X2(acc2[p][2], P20, wd[9]);
                    FMA_F32X2(acc2[p][2], P21, wd[7]);
                    FMA_F32X2(acc2[p][2], P22, wd[5]);
                    // (py=1,px=1): 4 taps
                    FMA_F32X2(acc2[p][3], P11, wd[18]);
                    FMA_F32X2(acc2[p][3], P12, wd[16]);
                    FMA_F32X2(acc2[p][3], P21, wd[8]);
                    FMA_F32X2(acc2[p][3], P22, wd[6]);
                }
                #undef PAIR_AT
            }
        }
    }

    if (co >= COUT) return;
    const int x = x0 + lane;

    const float bias = bq[co];
    const float m    = mul[co];
    float addA, invA, clpv = 0.f, sclv = 0.f, addB = 0.f, invB = 0.f;
    if (stage < 3) {
        addA = g_params[stage*6+0]; invA = g_params[stage*6+1];
        clpv = g_params[stage*6+2]; sclv = g_params[stage*6+3];
        addB = g_params[stage*6+4]; invB = g_params[stage*6+5];
    } else {
        addA = g_params[18]; invA = g_params[19];
    }
    const int OW = 2 * W;
    #pragma unroll
    for (int p = 0; p < PH; p++) {
        #pragma unroll
        for (int q = 0; q < 4; q++) {
            int py = q >> 1, px = q & 1;
            float vL, vH;
            UNPACK_F32X2(vL, vH, acc2[p][q]);
            #pragma unroll
            for (int h = 0; h < 2; h++) {
                float v = (h == 0) ? vL : vH;
                int oy = 2 * (y0 + base + p + h * PH) + py;
                v = (v + bias) * m;
                v = floorf((v + addA) * invA);
                if (stage < 3) {
                    v = fminf(fmaxf(v, 0.f), clpv);
                    v = floorf((v * sclv + addB) * invB);
                } else {
                    v = v / 255.0f;
                }
                out[(size_t)co * (4 * HW) + (size_t)oy * OW + (2 * x + px)] = v;
            }
        }
    }
}

// ---------------- host launcher (graph-capturable: kernel launches only) -------
extern "C" void kernel_launch(void* const* d_in, const int* in_sizes, int n_in,
                              void* d_out, int out_size)
{
    const float* x     = (const float*)d_in[0];
    const float* w1    = (const float*)d_in[1];
    const float* b1    = (const float*)d_in[2];
    const float* w2    = (const float*)d_in[3];
    const float* b2    = (const float*)d_in[4];
    const float* w3    = (const float*)d_in[5];
    const float* b3    = (const float*)d_in[6];
    const float* w4    = (const float*)d_in[7];
    const float* b4    = (const float*)d_in[8];
    const float* m0    = (const float*)d_in[9];
    const float* m1    = (const float*)d_in[10];
    const float* m2    = (const float*)d_in[11];
    const float* m3    = (const float*)d_in[12];
    const float* relus = (const float*)d_in[13];
    const int*   dvds  = (const int*)d_in[14];
    const int*   bitsp = (n_in > 15) ? (const int*)d_in[15] : nullptr;

    float *w1q, *w2q, *w3q, *w4q, *b1q, *b2q, *b3q, *b4q, *a0, *a1, *a2;
    cudaGetSymbolAddress((void**)&w1q, g_w1q);
    cudaGetSymbolAddress((void**)&w2q, g_w2q);
    cudaGetSymbolAddress((void**)&w3q, g_w3q);
    cudaGetSymbolAddress((void**)&w4q, g_w4q);
    cudaGetSymbolAddress((void**)&b1q, g_b1q);
    cudaGetSymbolAddress((void**)&b2q, g_b2q);
    cudaGetSymbolAddress((void**)&b3q, g_b3q);
    cudaGetSymbolAddress((void**)&b4q, g_b4q);
    cudaGetSymbolAddress((void**)&a0,  g_a0);
    cudaGetSymbolAddress((void**)&a1,  g_a1);
    cudaGetSymbolAddress((void**)&a2,  g_a2);

    auto q = [](const float* s, float* d, int n) {
        quant_kernel<<<(n + 255) / 256, 256>>>(s, d, n);
    };
    q(w1, w1q, 320*192*25);
    q(w2, w2q, 192*192*25);
    q(w3, w3q, 192*192*25);
    q(w4, w4q, 192*3*25);
    q(b1, b1q, 192);
    q(b2, b2q, 192);
    q(b3, b3q, 192);
    q(b4, b4q, 3);
    prep_kernel<<<1, 1>>>(relus, dvds, bitsp);

    // L1: 320ch 48x48 -> 192ch 96x96
    deconv_kernel<8,1><<<dim3(2, 6, 24), 256>>>(x,  a0, w1q, b1q, m0, 320, 192,  48,  48, 0);
    // L2: 192ch 96x96 -> 192ch 192x192
    deconv_kernel<8,1><<<dim3(3, 12, 24), 256>>>(a0, a1, w2q, b2q, m1, 192, 192,  96,  96, 1);
    // L3: 192ch 192x192 -> 192ch 384x384
    deconv_kernel<8,1><<<dim3(6, 24, 24), 256>>>(a1, a2, w3q, b3q, m2, 192, 192, 192, 192, 2);
    // L4: 192ch 384x384 -> 3ch 768x768 (final quant + /255), 4 co-slots x 2 y-subtiles
    deconv_kernel<4,2><<<dim3(12, 48, 1), 256>>>(a2, (float*)d_out, w4q, b4q, m3, 192, 3, 384, 384, 3);
}